// round 9
// baseline (speedup 1.0000x reference)
#include <cuda_runtime.h>
#include <cstdint>

// BinLinear: out = input @ sign(tanh(weight)), weight_b in {-1,+1}.
// Identity: out[n,o] = S[n] - 2*T[n,o], S[n]=rowsum(input row n),
//           T[n,o]  = sum of x[n,k] over k where weight[k,o] < 0.
// Exact fp32 products; only summation order differs from reference.
//
// Structure (R9): fill no longer depends on binarize. fill writes S[n]
// everywhere; a fixup pass corrects columns containing -1 weights (none on
// this dataset -> fixup fast-exits). This lets binarize (load-bound, idle
// store path) fuse with fill (store-bound, idle load path).
//
// Shapes fixed: M=8192, K=2048 (num_ip), N=2048 (num_op).

#define MDIM 8192
#define KDIM 2048
#define NDIM 2048
#define NQ   (NDIM / 4)      // 512 column quads
#define KB4  (KDIM / 4)      // 512 k-groups of 4 (16-bit mask words)
#define FULL 0xffffffffu

// Scratch (no cudaMalloc). Zero-initialized; atomics OR-idempotent so every
// graph replay reproduces identical state.
// g_mask16[kb4*NQ + c4]: bit (j*4+e) = sign of weight[kb4*4+j][c4*4+e] (1 => -1).
__device__ uint16_t g_mask16[KB4 * NQ];  // 512 KB
__device__ uint32_t g_negq[NQ];          // per-quad OR of mask words (rare path)
__device__ uint32_t g_anyflag;           // nonzero iff any negative weight
__device__ float    g_S[MDIM];           // row sums

// ---------------------------------------------------------------------------
// Kernel 1: row sums. One warp per row: 16 independent streaming float4
// loads, shuffle reduce, one store. 8192 warps = 1024 blocks x 256.
// Measured 10.5us (~6.1 TB/s) — near read floor.
// ---------------------------------------------------------------------------
__global__ void __launch_bounds__(256) rowsum_kernel(const float* __restrict__ x) {
    int wid  = blockIdx.x * (blockDim.x >> 5) + (threadIdx.x >> 5);
    int lane = threadIdx.x & 31;
    const float4* xrow4 = (const float4*)(x + (size_t)wid * KDIM);

    float s = 0.0f;
    #pragma unroll
    for (int i = 0; i < 16; i++) {
        float4 v = __ldcs(&xrow4[lane + 32 * i]);
        s += (v.x + v.y) + (v.z + v.w);
    }
    #pragma unroll
    for (int ofs = 16; ofs; ofs >>= 1)
        s += __shfl_xor_sync(FULL, s, ofs);
    if (lane == 0) g_S[wid] = s;
}

// ---------------------------------------------------------------------------
// Kernel 2: fused fill + binarize. 2048 blocks, alternating roles:
//   even bid -> fill block:    8 warps, warp-per-row, 16 STG.128 of S[row]
//   odd  bid -> binarize block: thread owns (quad c4, 4 k's): 4 LDG.128,
//               pack 16 sign bits, one 2B store (+ idempotent atomics if neg)
// fill saturates the store path; binarize rides the idle load path.
// ---------------------------------------------------------------------------
__global__ void __launch_bounds__(256) fillbin_kernel(const float4* __restrict__ w4,
                                                      float* __restrict__ out) {
    int bid = blockIdx.x;
    if ((bid & 1) == 0) {
        // ---- fill: warp per row ----
        int row  = (bid >> 1) * 8 + (threadIdx.x >> 5);
        int lane = threadIdx.x & 31;
        float s = g_S[row];                          // broadcast, L2-hot
        float4 val = make_float4(s, s, s, s);
        float4* orow4 = (float4*)(out + (size_t)row * NDIM);
        #pragma unroll
        for (int i = 0; i < 16; i++)
            __stcs(&orow4[lane + 32 * i], val);      // streaming stores
    } else {
        // ---- binarize: thread owns (c4, 4 k's) ----
        int tid = (bid >> 1) * 256 + threadIdx.x;
        int c4  = tid & (NQ - 1);                    // fastest -> coalesced
        int kb4 = tid >> 9;                          // 0..511
        const float4* base = w4 + (size_t)(kb4 * 4) * NQ + c4;

        uint32_t bits = 0;
        #pragma unroll
        for (int j = 0; j < 4; j++) {
            float4 v = __ldcs(&base[(size_t)j * NQ]);
            uint32_t b = (uint32_t)(v.x < 0.0f)
                       | ((uint32_t)(v.y < 0.0f) << 1)
                       | ((uint32_t)(v.z < 0.0f) << 2)
                       | ((uint32_t)(v.w < 0.0f) << 3);
            bits |= b << (j * 4);
        }
        g_mask16[kb4 * NQ + c4] = (uint16_t)bits;    // coalesced 2B store

        if (bits) {                                  // rare path (idempotent)
            atomicOr(&g_negq[c4], bits);
            atomicOr(&g_anyflag, 1u);
        }
    }
}

// ---------------------------------------------------------------------------
// Kernel 3: fixup. Fast-exits when no negative weights exist (dataset case:
// one broadcast load per thread, ~launch overhead only). General case: block
// per column quad; overwrites affected elements with the exact value
// S[n] - 2*T[n,c] recomputed from input + mask (no read-modify-write).
// ---------------------------------------------------------------------------
__global__ void __launch_bounds__(256) fixup_kernel(const float* __restrict__ x,
                                                    float* __restrict__ out) {
    if (g_anyflag == 0) return;                      // broadcast, L2-hot

    int c4 = blockIdx.x;                             // 512 blocks = NQ
    uint32_t q = g_negq[c4];
    if (q == 0) return;

    for (int n = threadIdx.x; n < MDIM; n += 256) {
        const float* xrow = x + (size_t)n * KDIM;
        float s = g_S[n];
        #pragma unroll
        for (int e = 0; e < 4; e++) {
            if ((q >> e) & 0x1111u) {
                float T = 0.0f;
                for (int kb4 = 0; kb4 < KB4; kb4++) {
                    uint32_t word = g_mask16[kb4 * NQ + c4];
                    uint32_t sel = (word >> e) & 0x1111u;
                    while (sel) {
                        int b = __ffs(sel) - 1;      // b = j*4
                        sel &= sel - 1;
                        T += xrow[kb4 * 4 + (b >> 2)];
                    }
                }
                out[(size_t)n * NDIM + c4 * 4 + e] = s - 2.0f * T;
            }
        }
    }
}

extern "C" void kernel_launch(void* const* d_in, const int* in_sizes, int n_in,
                              void* d_out, int out_size) {
    const float* input  = (const float*)d_in[0];   // [8192, 2048]
    const float* weight = (const float*)d_in[1];   // [2048, 2048]
    float* out = (float*)d_out;                    // [8192, 2048]

    rowsum_kernel<<<MDIM / 8, 256>>>(input);                          // 1024 blocks
    fillbin_kernel<<<2048, 256>>>((const float4*)weight, out);        // 1024+1024
    fixup_kernel<<<NQ, 256>>>(input, out);                            // 512 blocks
}

// round 10
// speedup vs baseline: 1.2891x; 1.2891x over previous
#include <cuda_runtime.h>
#include <cstdint>

// BinLinear: out = input @ sign(tanh(weight)), weight_b in {-1,+1}.
// Identity: out[n,o] = S[n] - 2*T[n,o], S[n]=rowsum(input row n),
//           T[n,o]  = sum of x[n,k] over k where weight[k,o] < 0.
// Exact fp32 products; only summation order differs from reference.
//
// R10 structure: ONE mega kernel carries all 144MB of streaming traffic
// (1024 rowfill blocks: read row -> S -> write row; 512 binarize blocks:
// weight -> sign mask), paying launch/ramp overhead once instead of 3x.
// A fixup pass (fast-exits when no negative weights: the dataset case)
// restores exact values for any column containing a -1 weight.
//
// Shapes fixed: M=8192, K=2048 (num_ip), N=2048 (num_op).

#define MDIM 8192
#define KDIM 2048
#define NDIM 2048
#define NQ   (NDIM / 4)      // 512 column quads
#define KB   (KDIM / 8)      // 256 k-groups of 8 (32-bit mask words)
#define FULL 0xffffffffu

// Scratch (no cudaMalloc). Zero-initialized; atomics OR-idempotent so every
// graph replay reproduces identical state.
// g_mask[kb*NQ + c4]: bit (j*4+e) = sign of weight[kb*8+j][c4*4+e] (1 => -1).
__device__ uint32_t g_mask[KB * NQ];     // 512 KB
__device__ uint32_t g_negq[NQ];          // per-quad OR of mask words (rare path)
__device__ uint32_t g_anyflag;           // nonzero iff any negative weight
__device__ float    g_S[MDIM];           // row sums (read by fixup)

// ---------------------------------------------------------------------------
// Mega kernel: 1536 blocks, roles interleaved 2:1.
//   bid%3 < 2  -> rowfill block (8 warps, warp-per-row):
//                 16 evict-first LDG.128 -> shuffle reduce -> S ->
//                 16 plain STG.128 (let output dirty L2; no DRAM pressure).
//   bid%3 == 2 -> binarize block: thread owns (quad c4, 8 k's):
//                 8 evict-first LDG.128, pack 32 sign bits, 1 word store
//                 (+ idempotent atomics only if negatives exist).
// ---------------------------------------------------------------------------
__global__ void __launch_bounds__(256) mega_kernel(const float4* __restrict__ w4,
                                                   const float* __restrict__ x,
                                                   float* __restrict__ out) {
    int bid = blockIdx.x;
    int g = bid / 3;
    int rem = bid - g * 3;

    if (rem < 2) {
        // ---- rowfill: one-pass read row -> S -> write row ----
        int rb   = g * 2 + rem;                      // 0..1023
        int row  = rb * 8 + (threadIdx.x >> 5);
        int lane = threadIdx.x & 31;
        const float4* xrow4 = (const float4*)(x + (size_t)row * KDIM);

        float s = 0.0f;
        #pragma unroll
        for (int half = 0; half < 2; half++) {       // 2 batches of 8 in flight
            float4 v[8];
            #pragma unroll
            for (int i = 0; i < 8; i++)
                v[i] = __ldcs(&xrow4[lane + 32 * (half * 8 + i)]);
            #pragma unroll
            for (int i = 0; i < 8; i++)
                s += (v[i].x + v[i].y) + (v[i].z + v[i].w);
        }
        #pragma unroll
        for (int ofs = 16; ofs; ofs >>= 1)
            s += __shfl_xor_sync(FULL, s, ofs);      // all lanes hold S
        if (lane == 0) g_S[row] = s;

        float4 val = make_float4(s, s, s, s);
        float4* orow4 = (float4*)(out + (size_t)row * NDIM);
        #pragma unroll
        for (int i = 0; i < 16; i++)
            orow4[lane + 32 * i] = val;              // plain stores -> L2
    } else {
        // ---- binarize: thread owns (c4, 8 k's) ----
        int tid = g * 256 + threadIdx.x;             // 0..131071
        int c4  = tid & (NQ - 1);                    // fastest -> coalesced
        int kb  = tid >> 9;                          // 0..255
        const float4* base = w4 + (size_t)(kb * 8) * NQ + c4;

        uint32_t bits = 0;
        #pragma unroll
        for (int j = 0; j < 8; j++) {
            float4 v = __ldcs(&base[(size_t)j * NQ]);
            uint32_t b = (uint32_t)(v.x < 0.0f)
                       | ((uint32_t)(v.y < 0.0f) << 1)
                       | ((uint32_t)(v.z < 0.0f) << 2)
                       | ((uint32_t)(v.w < 0.0f) << 3);
            bits |= b << (j * 4);
        }
        g_mask[kb * NQ + c4] = bits;                 // coalesced word store

        if (bits) {                                  // rare path (idempotent)
            atomicOr(&g_negq[c4], bits);
            atomicOr(&g_anyflag, 1u);
        }
    }
}

// ---------------------------------------------------------------------------
// Fixup: fast-exits when no negative weights exist (dataset case: one
// broadcast load, ~launch overhead only). General case: block per column
// quad; overwrites affected elements with the exact S[n] - 2*T[n,c]
// recomputed from input + mask (pure overwrite, no RMW -> deterministic).
// ---------------------------------------------------------------------------
__global__ void __launch_bounds__(256) fixup_kernel(const float* __restrict__ x,
                                                    float* __restrict__ out) {
    if (g_anyflag == 0) return;                      // broadcast, L2-hot

    int c4 = blockIdx.x;                             // 512 blocks = NQ
    uint32_t q = g_negq[c4];
    if (q == 0) return;

    for (int n = threadIdx.x; n < MDIM; n += 256) {
        const float* xrow = x + (size_t)n * KDIM;
        float s = g_S[n];
        #pragma unroll
        for (int e = 0; e < 4; e++) {
            if ((q >> e) & 0x11111111u) {
                float T = 0.0f;
                for (int kb = 0; kb < KB; kb++) {
                    uint32_t word = g_mask[kb * NQ + c4];
                    uint32_t sel = (word >> e) & 0x11111111u;
                    while (sel) {
                        int b = __ffs(sel) - 1;      // b = j*4
                        sel &= sel - 1;
                        T += xrow[kb * 8 + (b >> 2)];
                    }
                }
                out[(size_t)n * NDIM + c4 * 4 + e] = s - 2.0f * T;
            }
        }
    }
}

extern "C" void kernel_launch(void* const* d_in, const int* in_sizes, int n_in,
                              void* d_out, int out_size) {
    const float* input  = (const float*)d_in[0];   // [8192, 2048]
    const float* weight = (const float*)d_in[1];   // [2048, 2048]
    float* out = (float*)d_out;                    // [8192, 2048]

    mega_kernel<<<1536, 256>>>((const float4*)weight, input, out);
    fixup_kernel<<<NQ, 256>>>(input, out);
}